// round 2
// baseline (speedup 1.0000x reference)
#include <cuda_runtime.h>
#include <math.h>

#define Bn 2
#define Dn 192
#define Hn 64
#define Wn 64
#define Ln 4096
#define Kn 8
#define Nn 16
#define Rn 6
#define Cn 38   // R + 2N

// Scratch (device globals: allocation-free rule)
__device__ float g_delta[(size_t)Bn*Kn*Dn*Ln];   // 50.3 MB  softplus(dt)
__device__ float g_BC[(size_t)Bn*Kn*32*Ln];      // 8.4 MB   rows 0..15 = B, 16..31 = C
__device__ float g_ys[(size_t)Bn*Kn*Dn*Ln];      // 50.3 MB  scan outputs
__device__ float g_y[(size_t)Bn*Dn*Ln];          // 6.3 MB   merged (pre-LN), [b][d][l]

// Direction index map: xs[b,k,d,l] == x[b,d,map_idx(k,l)]
//  k0: row-major      k1: transpose      k4: diag (h+w)      k5: anti-diag (w-h)
//  k2,3,6,7 = reversed versions (l -> L-1-l)
__device__ __forceinline__ int map_idx(int k, int l){
    int lr = ((k >> 1) & 1) ? (Ln - 1 - l) : l;
    int type = (k & 1) | ((k & 4) >> 1);
    int a = lr >> 6, b = lr & 63;
    switch(type){
      case 0:  return lr;
      case 1:  return b * Wn + a;
      case 2:  return b * Wn + ((a + b) & 63);
      default: return b * Wn + ((a - b) & 63);
    }
}

// ---------------------------------------------------------------------------
// Kernel A: fused projection. For each (b,k,l): x_dbl[c] = sum_d W[k,c,d]*x[b,d,idx_k(l)]
// then delta = softplus(dtW @ x_dbl[0:6] + bias), B/C = x_dbl[6:38].
// Block = 256 threads = 4 c-groups x 64 l.  x gathered into smem in 4 d-passes of 48.
// ---------------------------------------------------------------------------
__global__ void __launch_bounds__(256) kproj(const float* __restrict__ x,
                                             const float* __restrict__ xw,
                                             const float* __restrict__ dtw,
                                             const float* __restrict__ dtb){
    __shared__ float sW[Cn*Dn];     // 7296 floats
    __shared__ float sdtW[Dn*Rn];   // 1152
    __shared__ float sbias[Dn];     // 192
    __shared__ float sxt[48*64];    // 3072
    __shared__ float sdt[Rn*64];    // 384   (total 48,384 B < 48 KB static)

    int tid = threadIdx.x;
    int lt = blockIdx.x, k = blockIdx.y, b = blockIdx.z;
    int lq = tid & 63, g = tid >> 6;             // g uniform per warp

    for(int i=tid;i<Cn*Dn;i+=256) sW[i]   = xw[k*Cn*Dn + i];
    for(int i=tid;i<Dn*Rn;i+=256) sdtW[i] = dtw[k*Dn*Rn + i];
    for(int i=tid;i<Dn;   i+=256) sbias[i]= dtb[k*Dn + i];

    float acc[10];
    #pragma unroll
    for(int j=0;j<10;j++) acc[j]=0.f;

    const float* xb = x + (size_t)b*Dn*Ln;
    for(int p=0;p<4;p++){
        __syncthreads();                         // also covers weight loads (p=0)
        int d0 = p*48;
        for(int i=tid;i<48*64;i+=256){
            int dd = i>>6, ll = i&63;
            sxt[i] = xb[(size_t)(d0+dd)*Ln + map_idx(k, lt*64 + ll)];
        }
        __syncthreads();
        for(int dd=0; dd<48; dd++){
            float xv = sxt[dd*64 + lq];
            int d = d0 + dd;
            #pragma unroll
            for(int j=0;j<10;j++){
                int c = g + 4*j;
                if(c < Cn) acc[j] = fmaf(sW[c*Dn + d], xv, acc[j]);
            }
        }
    }
    __syncthreads();

    // scatter: c<6 -> smem (dt rows), c in [6,38) -> g_BC
    float* bcBase = g_BC + ((size_t)(b*Kn+k))*32*Ln + (size_t)lt*64 + lq;
    #pragma unroll
    for(int j=0;j<10;j++){
        int c = g + 4*j;
        if(c < Rn)            sdt[c*64 + lq] = acc[j];
        else if(c < Cn)       bcBase[(size_t)(c-Rn)*Ln] = acc[j];
    }
    __syncthreads();

    // delta = softplus(dtW @ dt + bias), 192 d x 64 l
    float* dBase = g_delta + ((size_t)(b*Kn+k))*Dn*Ln + (size_t)lt*64;
    for(int i=tid;i<Dn*64;i+=256){
        int d = i>>6, ll = i&63;
        float v = sbias[d];
        #pragma unroll
        for(int r=0;r<Rn;r++) v = fmaf(sdtW[d*Rn+r], sdt[r*64+ll], v);
        float sp = fmaxf(v,0.f) + log1pf(expf(-fabsf(v)));
        dBase[(size_t)d*Ln + ll] = sp;
    }
}

// ---------------------------------------------------------------------------
// Kernel B: selective scan. Warp = 2 d x 16 n; lane holds one state h.
// Block = 512 thr = 32 d, grid = (6, K, B). Per-64-step chunk staged in smem (pitch 65).
// ---------------------------------------------------------------------------
__global__ void __launch_bounds__(512) kscan(const float* __restrict__ x,
                                             const float* __restrict__ A_logs,
                                             const float* __restrict__ Ds){
    __shared__ float sdl[32*65];
    __shared__ float su [32*65];
    __shared__ float sBC[32*65];
    __shared__ float sy [32*65];   // 33.3 KB total

    int tid = threadIdx.x;
    int dc = blockIdx.x, k = blockIdx.y, b = blockIdx.z;
    int wid = tid >> 5, lane = tid & 31;
    int dsel = lane >> 4, n = lane & 15;
    int dl = wid*2 + dsel;                 // 0..31 local d
    int dglob = dc*32 + dl;

    float a2 = -expf(A_logs[(k*Dn + dglob)*Nn + n]) * 1.4426950408889634f; // A*log2(e)
    float Dd = Ds[k*Dn + dglob];

    const float* dlt_g = g_delta + ((size_t)(b*Kn+k)*Dn + dc*32)*Ln;
    const float* bc_g  = g_BC   + (size_t)(b*Kn+k)*32*Ln;
    float*       ys_g  = g_ys   + ((size_t)(b*Kn+k)*Dn + dc*32)*Ln;
    const float* xb    = x + (size_t)b*Dn*Ln + (size_t)(dc*32)*Ln;

    float h = 0.f;
    int drow = dl*65;

    for(int c0=0;c0<Ln;c0+=64){
        for(int i=tid;i<2048;i+=512){
            int dd = i>>6, t = i&63;
            sdl[dd*65+t] = dlt_g[(size_t)dd*Ln + c0 + t];
            su [dd*65+t] = xb[(size_t)dd*Ln + map_idx(k, c0 + t)];
            sBC[dd*65+t] = bc_g[(size_t)dd*Ln + c0 + t];
        }
        __syncthreads();
        #pragma unroll 4
        for(int t=0;t<64;t++){
            float dlt = sdl[drow+t];
            float uu  = su [drow+t];
            float bt  = sBC[n*65+t];
            float ct  = sBC[(16+n)*65+t];
            float dA;
            asm("ex2.approx.ftz.f32 %0, %1;" : "=f"(dA) : "f"(dlt*a2));
            h = fmaf(h, dA, dlt*uu*bt);
            float p = h*ct;
            p += __shfl_xor_sync(0xffffffffu, p, 8);
            p += __shfl_xor_sync(0xffffffffu, p, 4);
            p += __shfl_xor_sync(0xffffffffu, p, 2);
            p += __shfl_xor_sync(0xffffffffu, p, 1);
            if(n == 0) sy[drow+t] = fmaf(Dd, uu, p);
        }
        __syncthreads();
        for(int i=tid;i<2048;i+=512){
            int dd=i>>6, t=i&63;
            ys_g[(size_t)dd*Ln + c0 + t] = sy[dd*65+t];
        }
        __syncthreads();
    }
}

// ---------------------------------------------------------------------------
// Kernel C: cross-merge. One block per (d, b) plane; all global reads coalesced,
// transpose/diagonal permutations resolved through a 64x65 smem tile.
// y[h,w] = ys0[l]+ys2[~l] + s13[w*64+h] + s46[((w-h)&63)*64+h] + s57[((w+h)&63)*64+h]
// ---------------------------------------------------------------------------
__global__ void __launch_bounds__(256) kmerge(){
    __shared__ float buf[64*65];
    int tid = threadIdx.x;
    int d = blockIdx.x, b = blockIdx.y;
    const float* base = g_ys + (size_t)b*Kn*Dn*Ln + (size_t)d*Ln;

    float acc[16];
    #pragma unroll
    for(int i=0;i<16;i++){
        int l = tid + i*256;
        acc[i] = base[(size_t)0*Dn*Ln + l] + base[(size_t)2*Dn*Ln + (Ln-1-l)];
    }
    // term 1+3 (transpose)
    for(int i=tid;i<Ln;i+=256)
        buf[(i>>6)*65 + (i&63)] = base[(size_t)1*Dn*Ln + i] + base[(size_t)3*Dn*Ln + (Ln-1-i)];
    __syncthreads();
    #pragma unroll
    for(int i=0;i<16;i++){
        int l = tid + i*256; int h = l>>6, w = l&63;
        acc[i] += buf[w*65 + h];
    }
    __syncthreads();
    // term 4+6 (diag)
    for(int i=tid;i<Ln;i+=256)
        buf[(i>>6)*65 + (i&63)] = base[(size_t)4*Dn*Ln + i] + base[(size_t)6*Dn*Ln + (Ln-1-i)];
    __syncthreads();
    #pragma unroll
    for(int i=0;i<16;i++){
        int l = tid + i*256; int h = l>>6, w = l&63;
        acc[i] += buf[((w-h)&63)*65 + h];
    }
    __syncthreads();
    // term 5+7 (anti-diag)
    for(int i=tid;i<Ln;i+=256)
        buf[(i>>6)*65 + (i&63)] = base[(size_t)5*Dn*Ln + i] + base[(size_t)7*Dn*Ln + (Ln-1-i)];
    __syncthreads();
    #pragma unroll
    for(int i=0;i<16;i++){
        int l = tid + i*256; int h = l>>6, w = l&63;
        acc[i] += buf[((w+h)&63)*65 + h];
    }
    float* yout = g_y + ((size_t)b*Dn + d)*Ln;
    #pragma unroll
    for(int i=0;i<16;i++) yout[tid + i*256] = acc[i];
}

// ---------------------------------------------------------------------------
// Kernel D: LayerNorm over D with [d][l] -> [l][d] transpose via smem tile (pitch 33).
// Block = 32 l positions, 256 thr = 8 d-groups x 32 l.
// ---------------------------------------------------------------------------
__global__ void __launch_bounds__(256) kln(const float* __restrict__ lnw,
                                           const float* __restrict__ lnb,
                                           float* __restrict__ out){
    __shared__ float sT[Dn*33];      // 25.3 KB
    __shared__ float sred[8*32], sredq[8*32];
    __shared__ float smu[32], srs[32];
    int tid = threadIdx.x;
    int lt = blockIdx.x, b = blockIdx.y;      // lt 0..127

    const float* ybase = g_y + (size_t)b*Dn*Ln + (size_t)lt*32;
    for(int i=tid;i<Dn*32;i+=256){
        int d = i>>5, ll = i&31;
        sT[d*33+ll] = ybase[(size_t)d*Ln + ll];
    }
    __syncthreads();

    int g = tid >> 5, ll = tid & 31;
    float s=0.f, sq=0.f;
    for(int d=g*24; d<g*24+24; d++){
        float v = sT[d*33+ll];
        s += v; sq = fmaf(v, v, sq);
    }
    sred[g*32+ll]=s; sredq[g*32+ll]=sq;
    __syncthreads();
    if(tid < 32){
        float S=0.f, Q=0.f;
        #pragma unroll
        for(int gg=0;gg<8;gg++){ S += sred[gg*32+tid]; Q += sredq[gg*32+tid]; }
        float mu  = S * (1.f/192.f);
        float var = Q * (1.f/192.f) - mu*mu;
        smu[tid] = mu;
        srs[tid] = rsqrtf(var + 1e-5f);
    }
    __syncthreads();

    float* obase = out + ((size_t)b*Ln + (size_t)lt*32)*Dn;
    for(int i=tid;i<32*Dn;i+=256){
        int l = i/Dn, d = i - l*Dn;            // consecutive tid -> consecutive d: coalesced
        float v = (sT[d*33+l] - smu[l]) * srs[l];
        obase[(size_t)l*Dn + d] = fmaf(v, lnw[d], lnb[d]);
    }
}

// ---------------------------------------------------------------------------
extern "C" void kernel_launch(void* const* d_in, const int* in_sizes, int n_in,
                              void* d_out, int out_size){
    const float* x   = (const float*)d_in[0];
    const float* xw  = (const float*)d_in[1];
    const float* dtw = (const float*)d_in[2];
    const float* dtb = (const float*)d_in[3];
    const float* alg = (const float*)d_in[4];
    const float* Ds  = (const float*)d_in[5];
    const float* lnw = (const float*)d_in[6];
    const float* lnb = (const float*)d_in[7];
    float* out = (float*)d_out;

    kproj <<<dim3(64, Kn, Bn), 256>>>(x, xw, dtw, dtb);
    kscan <<<dim3(6,  Kn, Bn), 512>>>(x, alg, Ds);
    kmerge<<<dim3(Dn, Bn),     256>>>();
    kln   <<<dim3(128, Bn),    256>>>(lnw, lnb, out);
}

// round 3
// speedup vs baseline: 1.6666x; 1.6666x over previous
#include <cuda_runtime.h>
#include <math.h>

#define Bn 2
#define Dn 192
#define Hn 64
#define Wn 64
#define Ln 4096
#define Kn 8
#define Nn 16
#define Rn 6
#define Cn 38   // R + 2N
#define G  8
#define SEG 512

// Scratch (device globals: allocation-free rule)
__device__ float g_delta[(size_t)Bn*Kn*Dn*Ln];   // 50.3 MB  softplus(dt)
__device__ float g_BC[(size_t)Bn*Kn*32*Ln];      // 8.4 MB   rows 0..15 = B, 16..31 = C
__device__ float g_ys[(size_t)Bn*Kn*Dn*Ln];      // 50.3 MB  scan outputs
__device__ float g_y[(size_t)Bn*Dn*Ln];          // 6.3 MB   merged (pre-LN)
__device__ float g_xT[(size_t)Bn*Dn*Ln];         // 6.3 MB   transpose copy
__device__ float g_xd[(size_t)Bn*Dn*Ln];         // 6.3 MB   diagonal copy
__device__ float g_xa[(size_t)Bn*Dn*Ln];         // 6.3 MB   anti-diagonal copy
__device__ float g_hend  [(size_t)Bn*Kn*G*Dn*Nn]; // segment summaries
__device__ float g_P     [(size_t)Bn*Kn*G*Dn*Nn];
__device__ float g_hstart[(size_t)Bn*Kn*G*Dn*Nn];

// direction decode: rev = (k>>1)&1 ; type = (k&1)|((k&4)>>1)
// type0 -> x, type1 -> xT, type2 -> xd, type3 -> xa ; all consecutive in l (or reversed)
__device__ __forceinline__ const float* dir_src(int type, const float* x){
    switch(type){
      case 0:  return x;
      case 1:  return g_xT;
      case 2:  return g_xd;
      default: return g_xa;
    }
}

// ---------------------------------------------------------------------------
// kprep: build xT/xd/xa so all later u-reads are coalesced rows.
//   xT[a*64+b] = x[b*64+a];  xd[a*64+b] = x[b*64+((a+b)&63)];  xa[a*64+b] = x[b*64+((a-b)&63)]
// ---------------------------------------------------------------------------
__global__ void __launch_bounds__(256) kprep(const float* __restrict__ x){
    __shared__ float s [64*65];
    __shared__ float s2[64*65];
    int tid = threadIdx.x, d = blockIdx.x, b = blockIdx.y;
    size_t off = ((size_t)b*Dn + d)*Ln;
    const float* src = x + off;
    for(int i=tid;i<4096;i+=256) s[(i>>6)*65 + (i&63)] = src[i];
    __syncthreads();
    for(int i=tid;i<4096;i+=256) g_xT[off+i] = s[(i&63)*65 + (i>>6)];
    for(int i=tid;i<4096;i+=256){ int bb=i>>6, a=i&63; s2[a*65+bb] = s[bb*65 + ((a+bb)&63)]; }
    __syncthreads();
    for(int i=tid;i<4096;i+=256) g_xd[off+i] = s2[(i>>6)*65 + (i&63)];
    __syncthreads();
    for(int i=tid;i<4096;i+=256){ int bb=i>>6, a=i&63; s2[a*65+bb] = s[bb*65 + ((a-bb)&63)]; }
    __syncthreads();
    for(int i=tid;i<4096;i+=256) g_xa[off+i] = s2[(i>>6)*65 + (i&63)];
}

// ---------------------------------------------------------------------------
// kproj: fused input projection (unchanged math; gathers now coalesced).
// ---------------------------------------------------------------------------
__global__ void __launch_bounds__(256) kproj(const float* __restrict__ x,
                                             const float* __restrict__ xw,
                                             const float* __restrict__ dtw,
                                             const float* __restrict__ dtb){
    __shared__ float sW[Cn*Dn];
    __shared__ float sdtW[Dn*Rn];
    __shared__ float sbias[Dn];
    __shared__ float sxt[48*64];
    __shared__ float sdt[Rn*64];

    int tid = threadIdx.x;
    int lt = blockIdx.x, k = blockIdx.y, b = blockIdx.z;
    int lq = tid & 63, g = tid >> 6;

    for(int i=tid;i<Cn*Dn;i+=256) sW[i]   = xw[k*Cn*Dn + i];
    for(int i=tid;i<Dn*Rn;i+=256) sdtW[i] = dtw[k*Dn*Rn + i];
    for(int i=tid;i<Dn;   i+=256) sbias[i]= dtb[k*Dn + i];

    float acc[10];
    #pragma unroll
    for(int j=0;j<10;j++) acc[j]=0.f;

    int rev = (k>>1)&1;
    const float* usrc = dir_src((k&1)|((k&4)>>1), x) + (size_t)b*Dn*Ln;

    for(int p=0;p<4;p++){
        __syncthreads();
        int d0 = p*48;
        for(int i=tid;i<48*64;i+=256){
            int dd = i>>6, ll = i&63;
            int l  = lt*64 + ll;
            int lr = rev ? (Ln-1-l) : l;
            sxt[i] = usrc[(size_t)(d0+dd)*Ln + lr];
        }
        __syncthreads();
        for(int dd=0; dd<48; dd++){
            float xv = sxt[dd*64 + lq];
            int d = d0 + dd;
            #pragma unroll
            for(int j=0;j<10;j++){
                int c = g + 4*j;
                if(c < Cn) acc[j] = fmaf(sW[c*Dn + d], xv, acc[j]);
            }
        }
    }
    __syncthreads();

    float* bcBase = g_BC + ((size_t)(b*Kn+k))*32*Ln + (size_t)lt*64 + lq;
    #pragma unroll
    for(int j=0;j<10;j++){
        int c = g + 4*j;
        if(c < Rn)       sdt[c*64 + lq] = acc[j];
        else if(c < Cn)  bcBase[(size_t)(c-Rn)*Ln] = acc[j];
    }
    __syncthreads();

    float* dBase = g_delta + ((size_t)(b*Kn+k))*Dn*Ln + (size_t)lt*64;
    for(int i=tid;i<Dn*64;i+=256){
        int d = i>>6, ll = i&63;
        float v = sbias[d];
        #pragma unroll
        for(int r=0;r<Rn;r++) v = fmaf(sdtW[d*Rn+r], sdt[r*64+ll], v);
        float sp = fmaxf(v,0.f) + log1pf(expf(-fabsf(v)));
        dBase[(size_t)d*Ln + ll] = sp;
    }
}

// ---------------------------------------------------------------------------
// kpass1: per-segment scan (h0 = 0), emits h_end and P = exp2(a2 * sum(delta)).
// warp = 8 d x 4 lanes (4 states each). Block = 256 thr = 64 d. T=64 chunks.
// grid (3, G*K, B)
// ---------------------------------------------------------------------------
__global__ void __launch_bounds__(256) kpass1(const float* __restrict__ x,
                                              const float* __restrict__ A_logs){
    __shared__ float sdl[64*65];
    __shared__ float sdu[64*65];
    __shared__ float sB [16*65];
    int tid = threadIdx.x;
    int dc = blockIdx.x, g = blockIdx.y>>3, k = blockIdx.y&7, b = blockIdx.z;
    int wid = tid>>5, lane = tid&31, grp = lane>>2, sl = lane&3;
    int dl = wid*8 + grp, d = dc*64 + dl, n0 = sl*4;

    float a2[4], h[4] = {0.f,0.f,0.f,0.f};
    #pragma unroll
    for(int i=0;i<4;i++)
        a2[i] = -expf(A_logs[(k*Dn+d)*Nn + n0 + i]) * 1.4426950408889634f;

    int rev = (k>>1)&1;
    const float* usrc  = dir_src((k&1)|((k&4)>>1), x) + ((size_t)b*Dn + dc*64)*Ln;
    const float* dlt_g = g_delta + ((size_t)(b*Kn+k)*Dn + dc*64)*Ln + g*SEG;
    const float* Bg    = g_BC + (size_t)(b*Kn+k)*32*Ln + g*SEG;

    float sumdlt = 0.f;
    int drow = dl*65;

    for(int c0=0;c0<SEG;c0+=64){
        for(int i=tid;i<4096;i+=256){
            int dd = i>>6, t = i&63;
            float dv = dlt_g[(size_t)dd*Ln + c0 + t];
            int l  = g*SEG + c0 + t;
            int lr = rev ? (Ln-1-l) : l;
            float uv = usrc[(size_t)dd*Ln + lr];
            sdl[dd*65+t] = dv;
            sdu[dd*65+t] = dv*uv;
        }
        for(int i=tid;i<1024;i+=256){
            int n = i>>6, t = i&63;
            sB[n*65+t] = Bg[(size_t)n*Ln + c0 + t];
        }
        __syncthreads();
        #pragma unroll 4
        for(int t=0;t<64;t++){
            float dlt = sdl[drow+t];
            float du  = sdu[drow+t];
            sumdlt += dlt;
            #pragma unroll
            for(int i=0;i<4;i++){
                float bt = sB[(n0+i)*65 + t];
                float dA;
                asm("ex2.approx.ftz.f32 %0, %1;" : "=f"(dA) : "f"(dlt*a2[i]));
                h[i] = fmaf(h[i], dA, du*bt);
            }
        }
        __syncthreads();
    }
    size_t base = ((size_t)((b*Kn+k)*G + g))*Dn*Nn + (size_t)d*Nn + n0;
    float4 h4; h4.x=h[0]; h4.y=h[1]; h4.z=h[2]; h4.w=h[3];
    float4 P4;
    P4.x = exp2f(a2[0]*sumdlt); P4.y = exp2f(a2[1]*sumdlt);
    P4.z = exp2f(a2[2]*sumdlt); P4.w = exp2f(a2[3]*sumdlt);
    *(float4*)(g_hend + base) = h4;
    *(float4*)(g_P    + base) = P4;
}

// ---------------------------------------------------------------------------
// kcarry: compose segment summaries sequentially (tiny).
// ---------------------------------------------------------------------------
__global__ void __launch_bounds__(256) kcarry(){
    int idx = blockIdx.x*256 + threadIdx.x;
    if(idx >= Bn*Kn*Dn*Nn) return;
    int bk = idx / (Dn*Nn);
    int dn = idx - bk*(Dn*Nn);
    size_t base = (size_t)bk*G*Dn*Nn + dn;
    float hcur = 0.f;
    for(int g=0; g<G; g++){
        size_t o = base + (size_t)g*Dn*Nn;
        g_hstart[o] = hcur;
        hcur = hcur * g_P[o] + g_hend[o];
    }
}

// ---------------------------------------------------------------------------
// kpass2: full scan per segment with correct h_start, emits ys. T=32 chunks.
// grid (3, G*K, B)
// ---------------------------------------------------------------------------
__global__ void __launch_bounds__(256) kpass2(const float* __restrict__ x,
                                              const float* __restrict__ A_logs,
                                              const float* __restrict__ Ds){
    __shared__ float sdl[64*33];
    __shared__ float su [64*33];
    __shared__ float sy [64*33];
    __shared__ float sB [16*33];
    __shared__ float sC [16*33];
    int tid = threadIdx.x;
    int dc = blockIdx.x, g = blockIdx.y>>3, k = blockIdx.y&7, b = blockIdx.z;
    int wid = tid>>5, lane = tid&31, grp = lane>>2, sl = lane&3;
    int dl = wid*8 + grp, d = dc*64 + dl, n0 = sl*4;

    float a2[4];
    #pragma unroll
    for(int i=0;i<4;i++)
        a2[i] = -expf(A_logs[(k*Dn+d)*Nn + n0 + i]) * 1.4426950408889634f;
    float Dd = Ds[k*Dn + d];

    size_t sumb = ((size_t)((b*Kn+k)*G + g))*Dn*Nn + (size_t)d*Nn + n0;
    float4 h4 = *(const float4*)(g_hstart + sumb);
    float h[4] = {h4.x, h4.y, h4.z, h4.w};

    int rev = (k>>1)&1;
    const float* usrc  = dir_src((k&1)|((k&4)>>1), x) + ((size_t)b*Dn + dc*64)*Ln;
    const float* dlt_g = g_delta + ((size_t)(b*Kn+k)*Dn + dc*64)*Ln + g*SEG;
    const float* BCg   = g_BC + (size_t)(b*Kn+k)*32*Ln + g*SEG;
    float*       ys_g  = g_ys + ((size_t)(b*Kn+k)*Dn + dc*64)*Ln + g*SEG;

    int drow = dl*33;

    for(int c0=0;c0<SEG;c0+=32){
        for(int i=tid;i<2048;i+=256){
            int dd = i>>5, t = i&31;
            sdl[dd*33+t] = dlt_g[(size_t)dd*Ln + c0 + t];
            int l  = g*SEG + c0 + t;
            int lr = rev ? (Ln-1-l) : l;
            su[dd*33+t] = usrc[(size_t)dd*Ln + lr];
        }
        for(int i=tid;i<512;i+=256){
            int n = i>>5, t = i&31;
            sB[n*33+t] = BCg[(size_t)n*Ln + c0 + t];
            sC[n*33+t] = BCg[(size_t)(16+n)*Ln + c0 + t];
        }
        __syncthreads();
        #pragma unroll 4
        for(int t=0;t<32;t++){
            float dlt = sdl[drow+t];
            float uu  = su [drow+t];
            float du  = dlt*uu;
            #pragma unroll
            for(int i=0;i<4;i++){
                float bt = sB[(n0+i)*33 + t];
                float dA;
                asm("ex2.approx.ftz.f32 %0, %1;" : "=f"(dA) : "f"(dlt*a2[i]));
                h[i] = fmaf(h[i], dA, du*bt);
            }
            float p =           h[0]*sC[(n0+0)*33+t];
            p = fmaf(h[1], sC[(n0+1)*33+t], p);
            p = fmaf(h[2], sC[(n0+2)*33+t], p);
            p = fmaf(h[3], sC[(n0+3)*33+t], p);
            p += __shfl_xor_sync(0xffffffffu, p, 1);
            p += __shfl_xor_sync(0xffffffffu, p, 2);
            if(sl == 0) sy[drow+t] = fmaf(Dd, uu, p);
        }
        __syncthreads();
        for(int i=tid;i<2048;i+=256){
            int dd = i>>5, t = i&31;
            ys_g[(size_t)dd*Ln + c0 + t] = sy[dd*33+t];
        }
        __syncthreads();
    }
}

// ---------------------------------------------------------------------------
// kmerge: cross-merge via 64x65 smem tiles (unchanged).
// ---------------------------------------------------------------------------
__global__ void __launch_bounds__(256) kmerge(){
    __shared__ float buf[64*65];
    int tid = threadIdx.x;
    int d = blockIdx.x, b = blockIdx.y;
    const float* base = g_ys + (size_t)b*Kn*Dn*Ln + (size_t)d*Ln;

    float acc[16];
    #pragma unroll
    for(int i=0;i<16;i++){
        int l = tid + i*256;
        acc[i] = base[(size_t)0*Dn*Ln + l] + base[(size_t)2*Dn*Ln + (Ln-1-l)];
    }
    for(int i=tid;i<Ln;i+=256)
        buf[(i>>6)*65 + (i&63)] = base[(size_t)1*Dn*Ln + i] + base[(size_t)3*Dn*Ln + (Ln-1-i)];
    __syncthreads();
    #pragma unroll
    for(int i=0;i<16;i++){
        int l = tid + i*256; int h = l>>6, w = l&63;
        acc[i] += buf[w*65 + h];
    }
    __syncthreads();
    for(int i=tid;i<Ln;i+=256)
        buf[(i>>6)*65 + (i&63)] = base[(size_t)4*Dn*Ln + i] + base[(size_t)6*Dn*Ln + (Ln-1-i)];
    __syncthreads();
    #pragma unroll
    for(int i=0;i<16;i++){
        int l = tid + i*256; int h = l>>6, w = l&63;
        acc[i] += buf[((w-h)&63)*65 + h];
    }
    __syncthreads();
    for(int i=tid;i<Ln;i+=256)
        buf[(i>>6)*65 + (i&63)] = base[(size_t)5*Dn*Ln + i] + base[(size_t)7*Dn*Ln + (Ln-1-i)];
    __syncthreads();
    #pragma unroll
    for(int i=0;i<16;i++){
        int l = tid + i*256; int h = l>>6, w = l&63;
        acc[i] += buf[((w+h)&63)*65 + h];
    }
    float* yout = g_y + ((size_t)b*Dn + d)*Ln;
    #pragma unroll
    for(int i=0;i<16;i++) yout[tid + i*256] = acc[i];
}

// ---------------------------------------------------------------------------
// kln: LayerNorm over D with transpose (unchanged).
// ---------------------------------------------------------------------------
__global__ void __launch_bounds__(256) kln(const float* __restrict__ lnw,
                                           const float* __restrict__ lnb,
                                           float* __restrict__ out){
    __shared__ float sT[Dn*33];
    __shared__ float sred[8*32], sredq[8*32];
    __shared__ float smu[32], srs[32];
    int tid = threadIdx.x;
    int lt = blockIdx.x, b = blockIdx.y;

    const float* ybase = g_y + (size_t)b*Dn*Ln + (size_t)lt*32;
    for(int i=tid;i<Dn*32;i+=256){
        int d = i>>5, ll = i&31;
        sT[d*33+ll] = ybase[(size_t)d*Ln + ll];
    }
    __syncthreads();

    int g = tid >> 5, ll = tid & 31;
    float s=0.f, sq=0.f;
    for(int d=g*24; d<g*24+24; d++){
        float v = sT[d*33+ll];
        s += v; sq = fmaf(v, v, sq);
    }
    sred[g*32+ll]=s; sredq[g*32+ll]=sq;
    __syncthreads();
    if(tid < 32){
        float S=0.f, Q=0.f;
        #pragma unroll
        for(int gg=0;gg<8;gg++){ S += sred[gg*32+tid]; Q += sredq[gg*32+tid]; }
        float mu  = S * (1.f/192.f);
        float var = Q * (1.f/192.f) - mu*mu;
        smu[tid] = mu;
        srs[tid] = rsqrtf(var + 1e-5f);
    }
    __syncthreads();

    float* obase = out + ((size_t)b*Ln + (size_t)lt*32)*Dn;
    for(int i=tid;i<32*Dn;i+=256){
        int l = i/Dn, d = i - l*Dn;
        float v = (sT[d*33+l] - smu[l]) * srs[l];
        obase[(size_t)l*Dn + d] = fmaf(v, lnw[d], lnb[d]);
    }
}

// ---------------------------------------------------------------------------
extern "C" void kernel_launch(void* const* d_in, const int* in_sizes, int n_in,
                              void* d_out, int out_size){
    const float* x   = (const float*)d_in[0];
    const float* xw  = (const float*)d_in[1];
    const float* dtw = (const float*)d_in[2];
    const float* dtb = (const float*)d_in[3];
    const float* alg = (const float*)d_in[4];
    const float* Ds  = (const float*)d_in[5];
    const float* lnw = (const float*)d_in[6];
    const float* lnb = (const float*)d_in[7];
    float* out = (float*)d_out;

    kprep <<<dim3(Dn, Bn),        256>>>(x);
    kproj <<<dim3(64, Kn, Bn),    256>>>(x, xw, dtw, dtb);
    kpass1<<<dim3(3, G*Kn, Bn),   256>>>(x, alg);
    kcarry<<<192,                 256>>>();
    kpass2<<<dim3(3, G*Kn, Bn),   256>>>(x, alg, Ds);
    kmerge<<<dim3(Dn, Bn),        256>>>();
    kln   <<<dim3(128, Bn),       256>>>(lnw, lnb, out);
}

// round 4
// speedup vs baseline: 2.3336x; 1.4002x over previous
#include <cuda_runtime.h>
#include <math.h>

#define Bn 2
#define Dn 192
#define Hn 64
#define Wn 64
#define Ln 4096
#define Kn 8
#define Nn 16
#define Rn 6
#define Cn 38   // R + 2N
#define G  8
#define SEG 512
#define PIT 68  // smem pitch for 64-t rows (mult of 4, conflict-free phases)

// Scratch (device globals: allocation-free rule)
__device__ float g_delta[(size_t)Bn*Kn*Dn*Ln];   // 50.3 MB  softplus(dt)
__device__ float g_BC[(size_t)Bn*Kn*32*Ln];      // 8.4 MB   rows 0..15 = B, 16..31 = C
__device__ float g_ys[(size_t)Bn*Kn*Dn*Ln];      // 50.3 MB  scan outputs
__device__ float g_y[(size_t)Bn*Dn*Ln];          // 6.3 MB   merged (pre-LN)
__device__ float g_xT[(size_t)Bn*Dn*Ln];         // 6.3 MB   transpose copy
__device__ float g_xd[(size_t)Bn*Dn*Ln];         // 6.3 MB   diagonal copy
__device__ float g_xa[(size_t)Bn*Dn*Ln];         // 6.3 MB   anti-diagonal copy
__device__ float g_hend[(size_t)Bn*Kn*G*Dn*Nn];  // segment summaries
__device__ float g_P   [(size_t)Bn*Kn*G*Dn*Nn];

// direction decode: rev = (k>>1)&1 ; type = (k&1)|((k&4)>>1)
__device__ __forceinline__ const float* dir_src(int type, const float* x){
    switch(type){
      case 0:  return x;
      case 1:  return g_xT;
      case 2:  return g_xd;
      default: return g_xa;
    }
}

// ---------------------------------------------------------------------------
// kprep: build xT/xd/xa so all later u-reads are coalesced rows.
// ---------------------------------------------------------------------------
__global__ void __launch_bounds__(256) kprep(const float* __restrict__ x){
    __shared__ float s [64*65];
    __shared__ float s2[64*65];
    int tid = threadIdx.x, d = blockIdx.x, b = blockIdx.y;
    size_t off = ((size_t)b*Dn + d)*Ln;
    const float* src = x + off;
    for(int i=tid;i<4096;i+=256) s[(i>>6)*65 + (i&63)] = src[i];
    __syncthreads();
    for(int i=tid;i<4096;i+=256) g_xT[off+i] = s[(i&63)*65 + (i>>6)];
    for(int i=tid;i<4096;i+=256){ int bb=i>>6, a=i&63; s2[a*65+bb] = s[bb*65 + ((a+bb)&63)]; }
    __syncthreads();
    for(int i=tid;i<4096;i+=256) g_xd[off+i] = s2[(i>>6)*65 + (i&63)];
    __syncthreads();
    for(int i=tid;i<4096;i+=256){ int bb=i>>6, a=i&63; s2[a*65+bb] = s[bb*65 + ((a-bb)&63)]; }
    __syncthreads();
    for(int i=tid;i<4096;i+=256) g_xa[off+i] = s2[(i>>6)*65 + (i&63)];
}

// ---------------------------------------------------------------------------
// kproj: fused input projection. sxt laid [l][d] (pitch 36) for float4 LDS.
// ---------------------------------------------------------------------------
__global__ void __launch_bounds__(256) kproj(const float* __restrict__ x,
                                             const float* __restrict__ xw,
                                             const float* __restrict__ dtw,
                                             const float* __restrict__ dtb){
    __shared__ float sW[Cn*Dn];
    __shared__ float sdtW[Dn*Rn];
    __shared__ float sbias[Dn];
    __shared__ float sxt[64*36];
    __shared__ float sdt[Rn*64];

    int tid = threadIdx.x;
    int lt = blockIdx.x, k = blockIdx.y, b = blockIdx.z;
    int lq = tid & 63, g = tid >> 6;

    for(int i=tid;i<Cn*Dn;i+=256) sW[i]   = xw[k*Cn*Dn + i];
    for(int i=tid;i<Dn*Rn;i+=256) sdtW[i] = dtw[k*Dn*Rn + i];
    for(int i=tid;i<Dn;   i+=256) sbias[i]= dtb[k*Dn + i];

    float acc[10];
    #pragma unroll
    for(int j=0;j<10;j++) acc[j]=0.f;

    int rev = (k>>1)&1;
    const float* usrc = dir_src((k&1)|((k&4)>>1), x) + (size_t)b*Dn*Ln;

    for(int p=0;p<6;p++){
        __syncthreads();
        int d0 = p*32;
        for(int i=tid;i<32*64;i+=256){
            int dd = i>>6, ll = i&63;
            int l  = lt*64 + ll;
            int lr = rev ? (Ln-1-l) : l;
            sxt[ll*36 + dd] = usrc[(size_t)(d0+dd)*Ln + lr];
        }
        __syncthreads();
        for(int dd4=0; dd4<8; dd4++){
            float xv[4]; *(float4*)xv = *(const float4*)&sxt[lq*36 + dd4*4];
            int dbase = d0 + dd4*4;
            #pragma unroll
            for(int j=0;j<10;j++){
                int c = g + 4*j;
                if(c < Cn){
                    float w[4]; *(float4*)w = *(const float4*)&sW[c*Dn + dbase];
                    acc[j] = fmaf(w[0],xv[0], fmaf(w[1],xv[1],
                             fmaf(w[2],xv[2], fmaf(w[3],xv[3], acc[j]))));
                }
            }
        }
    }
    __syncthreads();

    float* bcBase = g_BC + ((size_t)(b*Kn+k))*32*Ln + (size_t)lt*64 + lq;
    #pragma unroll
    for(int j=0;j<10;j++){
        int c = g + 4*j;
        if(c < Rn)       sdt[c*64 + lq] = acc[j];
        else if(c < Cn)  bcBase[(size_t)(c-Rn)*Ln] = acc[j];
    }
    __syncthreads();

    float* dBase = g_delta + ((size_t)(b*Kn+k))*Dn*Ln + (size_t)lt*64;
    for(int i=tid;i<Dn*64;i+=256){
        int d = i>>6, ll = i&63;
        float v = sbias[d];
        #pragma unroll
        for(int r=0;r<Rn;r++) v = fmaf(sdtW[d*Rn+r], sdt[r*64+ll], v);
        float sp = fmaxf(v,0.f) + log1pf(expf(-fabsf(v)));
        dBase[(size_t)d*Ln + ll] = sp;
    }
}

// ---------------------------------------------------------------------------
// kpass1: per-segment local scan (h0=0), emits h_end and P = exp2(a2*sum delta).
// Block = 128 thr = 32 d (warp = 8 d x 4 lanes x 4 states). grid (6, G*K, B).
// ---------------------------------------------------------------------------
__global__ void __launch_bounds__(128) kpass1(const float* __restrict__ x,
                                              const float* __restrict__ A_logs){
    __shared__ float sdl[32*PIT];
    __shared__ float sdu[32*PIT];
    __shared__ float sB [64*16];
    int tid = threadIdx.x;
    int dc = blockIdx.x, g = blockIdx.y>>3, k = blockIdx.y&7, b = blockIdx.z;
    int wid = tid>>5, lane = tid&31, grp = lane>>2, sl = lane&3;
    int dl = wid*8 + grp, d = dc*32 + dl, n0 = sl*4;

    float a2[4], h[4] = {0.f,0.f,0.f,0.f};
    #pragma unroll
    for(int i=0;i<4;i++)
        a2[i] = -expf(A_logs[(k*Dn+d)*Nn + n0 + i]) * 1.4426950408889634f;

    int rev = (k>>1)&1;
    const float* usrc  = dir_src((k&1)|((k&4)>>1), x) + ((size_t)b*Dn + dc*32)*Ln;
    const float* dlt_g = g_delta + ((size_t)(b*Kn+k)*Dn + dc*32)*Ln + g*SEG;
    const float* Bg    = g_BC + (size_t)(b*Kn+k)*32*Ln + g*SEG;

    float sumdlt = 0.f;
    int drow = dl*PIT;

    for(int c0=0;c0<SEG;c0+=64){
        int l0 = g*SEG + c0;
        for(int i=tid;i<512;i+=128){
            int dd = i>>4, q = i&15;
            float dv[4]; *(float4*)dv = *(const float4*)(dlt_g + (size_t)dd*Ln + c0 + q*4);
            float uv[4];
            const float* urow = usrc + (size_t)dd*Ln;
            if(!rev){ *(float4*)uv = *(const float4*)(urow + l0 + q*4); }
            else { float4 r = *(const float4*)(urow + (Ln-4-l0-q*4));
                   uv[0]=r.w; uv[1]=r.z; uv[2]=r.y; uv[3]=r.x; }
            float du[4];
            #pragma unroll
            for(int j=0;j<4;j++) du[j] = dv[j]*uv[j];
            *(float4*)&sdl[dd*PIT + q*4] = *(float4*)dv;
            *(float4*)&sdu[dd*PIT + q*4] = *(float4*)du;
        }
        for(int i=tid;i<256;i+=128){
            int n = i>>4, q = i&15;
            float bv[4]; *(float4*)bv = *(const float4*)(Bg + (size_t)n*Ln + c0 + q*4);
            #pragma unroll
            for(int j=0;j<4;j++) sB[(q*4+j)*16 + n] = bv[j];
        }
        __syncthreads();
        for(int t4=0;t4<64;t4+=4){
            float dv[4]; *(float4*)dv = *(const float4*)&sdl[drow+t4];
            float du[4]; *(float4*)du = *(const float4*)&sdu[drow+t4];
            #pragma unroll
            for(int j=0;j<4;j++){
                float dlt = dv[j], duu = du[j];
                sumdlt += dlt;
                float bt[4]; *(float4*)bt = *(const float4*)&sB[(t4+j)*16 + n0];
                #pragma unroll
                for(int i=0;i<4;i++){
                    float dA;
                    asm("ex2.approx.ftz.f32 %0, %1;" : "=f"(dA) : "f"(dlt*a2[i]));
                    h[i] = fmaf(h[i], dA, duu*bt[i]);
                }
            }
        }
        __syncthreads();
    }
    size_t base = ((size_t)((b*Kn+k)*G + g))*Dn*Nn + (size_t)d*Nn + n0;
    float4 h4; h4.x=h[0]; h4.y=h[1]; h4.z=h[2]; h4.w=h[3];
    float4 P4;
    P4.x = exp2f(a2[0]*sumdlt); P4.y = exp2f(a2[1]*sumdlt);
    P4.z = exp2f(a2[2]*sumdlt); P4.w = exp2f(a2[3]*sumdlt);
    *(float4*)(g_hend + base) = h4;
    *(float4*)(g_P    + base) = P4;
}

// ---------------------------------------------------------------------------
// kpass2: full scan with fused carry (composes predecessor summaries), emits ys.
// Same block shape as kpass1. grid (6, G*K, B).
// ---------------------------------------------------------------------------
__global__ void __launch_bounds__(128) kpass2(const float* __restrict__ x,
                                              const float* __restrict__ A_logs,
                                              const float* __restrict__ Ds){
    __shared__ float sdl[32*PIT];
    __shared__ float su [32*PIT];
    __shared__ float sy [32*PIT];
    __shared__ float sB [64*16];
    __shared__ float sC [64*16];
    int tid = threadIdx.x;
    int dc = blockIdx.x, g = blockIdx.y>>3, k = blockIdx.y&7, b = blockIdx.z;
    int wid = tid>>5, lane = tid&31, grp = lane>>2, sl = lane&3;
    int dl = wid*8 + grp, d = dc*32 + dl, n0 = sl*4;

    float a2[4];
    #pragma unroll
    for(int i=0;i<4;i++)
        a2[i] = -expf(A_logs[(k*Dn+d)*Nn + n0 + i]) * 1.4426950408889634f;
    float Dd = Ds[k*Dn + d];

    // fused carry: compose inclusive prefix of segments 0..g-1
    float h[4] = {0.f,0.f,0.f,0.f};
    {
        size_t cb = ((size_t)(b*Kn+k)*G)*Dn*Nn + (size_t)d*Nn + n0;
        for(int gg=0; gg<g; gg++){
            float4 P4 = *(const float4*)(g_P    + cb + (size_t)gg*Dn*Nn);
            float4 E4 = *(const float4*)(g_hend + cb + (size_t)gg*Dn*Nn);
            h[0] = fmaf(h[0], P4.x, E4.x);
            h[1] = fmaf(h[1], P4.y, E4.y);
            h[2] = fmaf(h[2], P4.z, E4.z);
            h[3] = fmaf(h[3], P4.w, E4.w);
        }
    }

    int rev = (k>>1)&1;
    const float* usrc  = dir_src((k&1)|((k&4)>>1), x) + ((size_t)b*Dn + dc*32)*Ln;
    const float* dlt_g = g_delta + ((size_t)(b*Kn+k)*Dn + dc*32)*Ln + g*SEG;
    const float* BCg   = g_BC + (size_t)(b*Kn+k)*32*Ln + g*SEG;
    float*       ys_g  = g_ys + ((size_t)(b*Kn+k)*Dn + dc*32)*Ln + g*SEG;

    int drow = dl*PIT;

    for(int c0=0;c0<SEG;c0+=64){
        int l0 = g*SEG + c0;
        for(int i=tid;i<512;i+=128){
            int dd = i>>4, q = i&15;
            float4 dv = *(const float4*)(dlt_g + (size_t)dd*Ln + c0 + q*4);
            float4 uv;
            const float* urow = usrc + (size_t)dd*Ln;
            if(!rev){ uv = *(const float4*)(urow + l0 + q*4); }
            else { float4 r = *(const float4*)(urow + (Ln-4-l0-q*4));
                   uv.x=r.w; uv.y=r.z; uv.z=r.y; uv.w=r.x; }
            *(float4*)&sdl[dd*PIT + q*4] = dv;
            *(float4*)&su [dd*PIT + q*4] = uv;
        }
        for(int i=tid;i<256;i+=128){
            int n = i>>4, q = i&15;
            float bv[4]; *(float4*)bv = *(const float4*)(BCg + (size_t)n*Ln + c0 + q*4);
            float cv[4]; *(float4*)cv = *(const float4*)(BCg + (size_t)(16+n)*Ln + c0 + q*4);
            #pragma unroll
            for(int j=0;j<4;j++){ sB[(q*4+j)*16 + n] = bv[j]; sC[(q*4+j)*16 + n] = cv[j]; }
        }
        __syncthreads();
        for(int t4=0;t4<64;t4+=4){
            float dv[4]; *(float4*)dv = *(const float4*)&sdl[drow+t4];
            float uv[4]; *(float4*)uv = *(const float4*)&su [drow+t4];
            #pragma unroll
            for(int j=0;j<4;j++){
                float dlt = dv[j], uu = uv[j];
                float du = dlt*uu;
                float bt[4]; *(float4*)bt = *(const float4*)&sB[(t4+j)*16 + n0];
                float ct[4]; *(float4*)ct = *(const float4*)&sC[(t4+j)*16 + n0];
                float p = 0.f;
                #pragma unroll
                for(int i=0;i<4;i++){
                    float dA;
                    asm("ex2.approx.ftz.f32 %0, %1;" : "=f"(dA) : "f"(dlt*a2[i]));
                    h[i] = fmaf(h[i], dA, du*bt[i]);
                    p = fmaf(h[i], ct[i], p);
                }
                p += __shfl_xor_sync(0xffffffffu, p, 1);
                p += __shfl_xor_sync(0xffffffffu, p, 2);
                if(sl == 0) sy[drow+t4+j] = fmaf(Dd, uu, p);
            }
        }
        __syncthreads();
        for(int i=tid;i<512;i+=128){
            int dd = i>>4, q = i&15;
            *(float4*)(ys_g + (size_t)dd*Ln + c0 + q*4) = *(const float4*)&sy[dd*PIT + q*4];
        }
        __syncthreads();
    }
}

// ---------------------------------------------------------------------------
// kmerge: cross-merge via 64x65 smem tiles (pitch 65 keeps transpose reads
// conflict-free; memory-bound, kept scalar).
// ---------------------------------------------------------------------------
__global__ void __launch_bounds__(256) kmerge(){
    __shared__ float buf[64*65];
    int tid = threadIdx.x;
    int d = blockIdx.x, b = blockIdx.y;
    const float* base = g_ys + (size_t)b*Kn*Dn*Ln + (size_t)d*Ln;

    float acc[16];
    #pragma unroll
    for(int i=0;i<16;i++){
        int l = tid + i*256;
        acc[i] = base[(size_t)0*Dn*Ln + l] + base[(size_t)2*Dn*Ln + (Ln-1-l)];
    }
    for(int i=tid;i<Ln;i+=256)
        buf[(i>>6)*65 + (i&63)] = base[(size_t)1*Dn*Ln + i] + base[(size_t)3*Dn*Ln + (Ln-1-i)];
    __syncthreads();
    #pragma unroll
    for(int i=0;i<16;i++){
        int l = tid + i*256; int h = l>>6, w = l&63;
        acc[i] += buf[w*65 + h];
    }
    __syncthreads();
    for(int i=tid;i<Ln;i+=256)
        buf[(i>>6)*65 + (i&63)] = base[(size_t)4*Dn*Ln + i] + base[(size_t)6*Dn*Ln + (Ln-1-i)];
    __syncthreads();
    #pragma unroll
    for(int i=0;i<16;i++){
        int l = tid + i*256; int h = l>>6, w = l&63;
        acc[i] += buf[((w-h)&63)*65 + h];
    }
    __syncthreads();
    for(int i=tid;i<Ln;i+=256)
        buf[(i>>6)*65 + (i&63)] = base[(size_t)5*Dn*Ln + i] + base[(size_t)7*Dn*Ln + (Ln-1-i)];
    __syncthreads();
    #pragma unroll
    for(int i=0;i<16;i++){
        int l = tid + i*256; int h = l>>6, w = l&63;
        acc[i] += buf[((w+h)&63)*65 + h];
    }
    float* yout = g_y + ((size_t)b*Dn + d)*Ln;
    #pragma unroll
    for(int i=0;i<16;i++) yout[tid + i*256] = acc[i];
}

// ---------------------------------------------------------------------------
// kln: LayerNorm over D with transpose (unchanged).
// ---------------------------------------------------------------------------
__global__ void __launch_bounds__(256) kln(const float* __restrict__ lnw,
                                           const float* __restrict__ lnb,
                                           float* __restrict__ out){
    __shared__ float sT[Dn*33];
    __shared__ float sred[8*32], sredq[8*32];
    __shared__ float smu[32], srs[32];
    int tid = threadIdx.x;
    int lt = blockIdx.x, b = blockIdx.y;

    const float* ybase = g_y + (size_t)b*Dn*Ln + (size_t)lt*32;
    for(int i=tid;i<Dn*32;i+=256){
        int d = i>>5, ll = i&31;
        sT[d*33+ll] = ybase[(size_t)d*Ln + ll];
    }
    __syncthreads();

    int g = tid >> 5, ll = tid & 31;
    float s=0.f, sq=0.f;
    for(int d=g*24; d<g*24+24; d++){
        float v = sT[d*33+ll];
        s += v; sq = fmaf(v, v, sq);
    }
    sred[g*32+ll]=s; sredq[g*32+ll]=sq;
    __syncthreads();
    if(tid < 32){
        float S=0.f, Q=0.f;
        #pragma unroll
        for(int gg=0;gg<8;gg++){ S += sred[gg*32+tid]; Q += sredq[gg*32+tid]; }
        float mu  = S * (1.f/192.f);
        float var = Q * (1.f/192.f) - mu*mu;
        smu[tid] = mu;
        srs[tid] = rsqrtf(var + 1e-5f);
    }
    __syncthreads();

    float* obase = out + ((size_t)b*Ln + (size_t)lt*32)*Dn;
    for(int i=tid;i<32*Dn;i+=256){
        int l = i/Dn, d = i - l*Dn;
        float v = (sT[d*33+l] - smu[l]) * srs[l];
        obase[(size_t)l*Dn + d] = fmaf(v, lnw[d], lnb[d]);
    }
}

// ---------------------------------------------------------------------------
extern "C" void kernel_launch(void* const* d_in, const int* in_sizes, int n_in,
                              void* d_out, int out_size){
    const float* x   = (const float*)d_in[0];
    const float* xw  = (const float*)d_in[1];
    const float* dtw = (const float*)d_in[2];
    const float* dtb = (const float*)d_in[3];
    const float* alg = (const float*)d_in[4];
    const float* Ds  = (const float*)d_in[5];
    const float* lnw = (const float*)d_in[6];
    const float* lnb = (const float*)d_in[7];
    float* out = (float*)d_out;

    kprep <<<dim3(Dn, Bn),        256>>>(x);
    kproj <<<dim3(64, Kn, Bn),    256>>>(x, xw, dtw, dtb);
    kpass1<<<dim3(6, G*Kn, Bn),   128>>>(x, alg);
    kpass2<<<dim3(6, G*Kn, Bn),   128>>>(x, alg, Ds);
    kmerge<<<dim3(Dn, Bn),        256>>>();
    kln   <<<dim3(128, Bn),       256>>>(lnw, lnb, out);
}

// round 5
// speedup vs baseline: 2.4827x; 1.0639x over previous
#include <cuda_runtime.h>
#include <math.h>

#define Bn 2
#define Dn 192
#define Hn 64
#define Wn 64
#define Ln 4096
#define Kn 8
#define Nn 16
#define Rn 6
#define Cn 38   // R + 2N
#define G  16
#define SEG 256
#define PIT 68  // smem pitch for 64-t rows (pass1)
#define PT2 36  // smem pitch for 32-t rows (pass2)

// Scratch (device globals: allocation-free rule)
__device__ float g_delta[(size_t)Bn*Kn*Dn*Ln];   // 50.3 MB  softplus(dt)
__device__ float g_BC[(size_t)Bn*Kn*32*Ln];      // 8.4 MB   rows 0..15 = B, 16..31 = C
__device__ float g_ys[(size_t)Bn*Kn*Dn*Ln];      // 50.3 MB  scan outputs
__device__ float g_y[(size_t)Bn*Dn*Ln];          // 6.3 MB   merged (pre-LN)
__device__ float g_xT[(size_t)Bn*Dn*Ln];         // 6.3 MB   transpose copy
__device__ float g_xd[(size_t)Bn*Dn*Ln];         // 6.3 MB   diagonal copy
__device__ float g_xa[(size_t)Bn*Dn*Ln];         // 6.3 MB   anti-diagonal copy
__device__ float g_hend[(size_t)Bn*Kn*G*Dn*Nn];  // segment summaries
__device__ float g_P   [(size_t)Bn*Kn*G*Dn*Nn];

// direction decode: rev = (k>>1)&1 ; type = (k&1)|((k&4)>>1)
__device__ __forceinline__ const float* dir_src(int type, const float* x){
    switch(type){
      case 0:  return x;
      case 1:  return g_xT;
      case 2:  return g_xd;
      default: return g_xa;
    }
}

// ---------------------------------------------------------------------------
// kprep: build xT/xd/xa so all later u-reads are coalesced rows.
// ---------------------------------------------------------------------------
__global__ void __launch_bounds__(256) kprep(const float* __restrict__ x){
    __shared__ float s [64*65];
    __shared__ float s2[64*65];
    int tid = threadIdx.x, d = blockIdx.x, b = blockIdx.y;
    size_t off = ((size_t)b*Dn + d)*Ln;
    const float* src = x + off;
    for(int i=tid;i<4096;i+=256) s[(i>>6)*65 + (i&63)] = src[i];
    __syncthreads();
    for(int i=tid;i<4096;i+=256) g_xT[off+i] = s[(i&63)*65 + (i>>6)];
    for(int i=tid;i<4096;i+=256){ int bb=i>>6, a=i&63; s2[a*65+bb] = s[bb*65 + ((a+bb)&63)]; }
    __syncthreads();
    for(int i=tid;i<4096;i+=256) g_xd[off+i] = s2[(i>>6)*65 + (i&63)];
    __syncthreads();
    for(int i=tid;i<4096;i+=256){ int bb=i>>6, a=i&63; s2[a*65+bb] = s[bb*65 + ((a-bb)&63)]; }
    __syncthreads();
    for(int i=tid;i<4096;i+=256) g_xa[off+i] = s2[(i>>6)*65 + (i&63)];
}

// ---------------------------------------------------------------------------
// kproj: fused input projection. sxt laid [l][d] (pitch 36) for float4 LDS.
// ---------------------------------------------------------------------------
__global__ void __launch_bounds__(256) kproj(const float* __restrict__ x,
                                             const float* __restrict__ xw,
                                             const float* __restrict__ dtw,
                                             const float* __restrict__ dtb){
    __shared__ float sW[Cn*Dn];
    __shared__ float sdtW[Dn*Rn];
    __shared__ float sbias[Dn];
    __shared__ float sxt[64*36];
    __shared__ float sdt[Rn*64];

    int tid = threadIdx.x;
    int lt = blockIdx.x, k = blockIdx.y, b = blockIdx.z;
    int lq = tid & 63, g = tid >> 6;

    for(int i=tid;i<Cn*Dn;i+=256) sW[i]   = xw[k*Cn*Dn + i];
    for(int i=tid;i<Dn*Rn;i+=256) sdtW[i] = dtw[k*Dn*Rn + i];
    for(int i=tid;i<Dn;   i+=256) sbias[i]= dtb[k*Dn + i];

    float acc[10];
    #pragma unroll
    for(int j=0;j<10;j++) acc[j]=0.f;

    int rev = (k>>1)&1;
    const float* usrc = dir_src((k&1)|((k&4)>>1), x) + (size_t)b*Dn*Ln;

    for(int p=0;p<6;p++){
        __syncthreads();
        int d0 = p*32;
        for(int i=tid;i<32*64;i+=256){
            int dd = i>>6, ll = i&63;
            int l  = lt*64 + ll;
            int lr = rev ? (Ln-1-l) : l;
            sxt[ll*36 + dd] = usrc[(size_t)(d0+dd)*Ln + lr];
        }
        __syncthreads();
        for(int dd4=0; dd4<8; dd4++){
            float xv[4]; *(float4*)xv = *(const float4*)&sxt[lq*36 + dd4*4];
            int dbase = d0 + dd4*4;
            #pragma unroll
            for(int j=0;j<10;j++){
                int c = g + 4*j;
                if(c < Cn){
                    float w[4]; *(float4*)w = *(const float4*)&sW[c*Dn + dbase];
                    acc[j] = fmaf(w[0],xv[0], fmaf(w[1],xv[1],
                             fmaf(w[2],xv[2], fmaf(w[3],xv[3], acc[j]))));
                }
            }
        }
    }
    __syncthreads();

    float* bcBase = g_BC + ((size_t)(b*Kn+k))*32*Ln + (size_t)lt*64 + lq;
    #pragma unroll
    for(int j=0;j<10;j++){
        int c = g + 4*j;
        if(c < Rn)       sdt[c*64 + lq] = acc[j];
        else if(c < Cn)  bcBase[(size_t)(c-Rn)*Ln] = acc[j];
    }
    __syncthreads();

    float* dBase = g_delta + ((size_t)(b*Kn+k))*Dn*Ln + (size_t)lt*64;
    for(int i=tid;i<Dn*64;i+=256){
        int d = i>>6, ll = i&63;
        float v = sbias[d];
        #pragma unroll
        for(int r=0;r<Rn;r++) v = fmaf(sdtW[d*Rn+r], sdt[r*64+ll], v);
        float sp = fmaxf(v,0.f) + log1pf(expf(-fabsf(v)));
        dBase[(size_t)d*Ln + ll] = sp;
    }
}

// ---------------------------------------------------------------------------
// kpass1: per-segment local scan (h0=0), emits h_end and P = exp2(a2*sum delta).
// Block = 128 thr = 32 d (warp = 8 d x 4 lanes x 4 states). grid (6, G*K, B).
// T=64 chunks (smem 21.5 KB -> ~10 blocks/SM).
// ---------------------------------------------------------------------------
__global__ void __launch_bounds__(128) kpass1(const float* __restrict__ x,
                                              const float* __restrict__ A_logs){
    __shared__ float sdl[32*PIT];
    __shared__ float sdu[32*PIT];
    __shared__ float sB [64*16];
    int tid = threadIdx.x;
    int dc = blockIdx.x, g = blockIdx.y>>3, k = blockIdx.y&7, b = blockIdx.z;
    int wid = tid>>5, lane = tid&31, grp = lane>>2, sl = lane&3;
    int dl = wid*8 + grp, d = dc*32 + dl, n0 = sl*4;

    float a2[4], h[4] = {0.f,0.f,0.f,0.f};
    #pragma unroll
    for(int i=0;i<4;i++)
        a2[i] = -expf(A_logs[(k*Dn+d)*Nn + n0 + i]) * 1.4426950408889634f;

    int rev = (k>>1)&1;
    const float* usrc  = dir_src((k&1)|((k&4)>>1), x) + ((size_t)b*Dn + dc*32)*Ln;
    const float* dlt_g = g_delta + ((size_t)(b*Kn+k)*Dn + dc*32)*Ln + g*SEG;
    const float* Bg    = g_BC + (size_t)(b*Kn+k)*32*Ln + g*SEG;

    float sumdlt = 0.f;
    int drow = dl*PIT;

    for(int c0=0;c0<SEG;c0+=64){
        int l0 = g*SEG + c0;
        for(int i=tid;i<512;i+=128){
            int dd = i>>4, q = i&15;
            float dv[4]; *(float4*)dv = *(const float4*)(dlt_g + (size_t)dd*Ln + c0 + q*4);
            float uv[4];
            const float* urow = usrc + (size_t)dd*Ln;
            if(!rev){ *(float4*)uv = *(const float4*)(urow + l0 + q*4); }
            else { float4 r = *(const float4*)(urow + (Ln-4-l0-q*4));
                   uv[0]=r.w; uv[1]=r.z; uv[2]=r.y; uv[3]=r.x; }
            float du[4];
            #pragma unroll
            for(int j=0;j<4;j++) du[j] = dv[j]*uv[j];
            *(float4*)&sdl[dd*PIT + q*4] = *(float4*)dv;
            *(float4*)&sdu[dd*PIT + q*4] = *(float4*)du;
        }
        for(int i=tid;i<256;i+=128){
            int n = i>>4, q = i&15;
            float bv[4]; *(float4*)bv = *(const float4*)(Bg + (size_t)n*Ln + c0 + q*4);
            #pragma unroll
            for(int j=0;j<4;j++) sB[(q*4+j)*16 + n] = bv[j];
        }
        __syncthreads();
        for(int t4=0;t4<64;t4+=4){
            float dv[4]; *(float4*)dv = *(const float4*)&sdl[drow+t4];
            float du[4]; *(float4*)du = *(const float4*)&sdu[drow+t4];
            #pragma unroll
            for(int j=0;j<4;j++){
                float dlt = dv[j], duu = du[j];
                sumdlt += dlt;
                float bt[4]; *(float4*)bt = *(const float4*)&sB[(t4+j)*16 + n0];
                #pragma unroll
                for(int i=0;i<4;i++){
                    float dA;
                    asm("ex2.approx.ftz.f32 %0, %1;" : "=f"(dA) : "f"(dlt*a2[i]));
                    h[i] = fmaf(h[i], dA, duu*bt[i]);
                }
            }
        }
        __syncthreads();
    }
    size_t base = ((size_t)((b*Kn+k)*G + g))*Dn*Nn + (size_t)d*Nn + n0;
    float4 h4; h4.x=h[0]; h4.y=h[1]; h4.z=h[2]; h4.w=h[3];
    float4 P4;
    P4.x = exp2f(a2[0]*sumdlt); P4.y = exp2f(a2[1]*sumdlt);
    P4.z = exp2f(a2[2]*sumdlt); P4.w = exp2f(a2[3]*sumdlt);
    *(float4*)(g_hend + base) = h4;
    *(float4*)(g_P    + base) = P4;
}

// ---------------------------------------------------------------------------
// kpass2: full scan with fused carry, emits ys.
// T=32 chunks (smem 17.9 KB -> ~12 blocks/SM; occupancy driven by 1536-block grid).
// ---------------------------------------------------------------------------
__global__ void __launch_bounds__(128) kpass2(const float* __restrict__ x,
                                              const float* __restrict__ A_logs,
                                              const float* __restrict__ Ds){
    __shared__ float sdl[32*PT2];
    __shared__ float su [32*PT2];
    __shared__ float sy [32*PT2];
    __shared__ float sB [32*16];
    __shared__ float sC [32*16];
    int tid = threadIdx.x;
    int dc = blockIdx.x, g = blockIdx.y>>3, k = blockIdx.y&7, b = blockIdx.z;
    int wid = tid>>5, lane = tid&31, grp = lane>>2, sl = lane&3;
    int dl = wid*8 + grp, d = dc*32 + dl, n0 = sl*4;

    float a2[4];
    #pragma unroll
    for(int i=0;i<4;i++)
        a2[i] = -expf(A_logs[(k*Dn+d)*Nn + n0 + i]) * 1.4426950408889634f;
    float Dd = Ds[k*Dn + d];

    // fused carry: compose inclusive prefix of segments 0..g-1
    float h[4] = {0.f,0.f,0.f,0.f};
    {
        size_t cb = ((size_t)(b*Kn+k)*G)*Dn*Nn + (size_t)d*Nn + n0;
        for(int gg=0; gg<g; gg++){
            float4 P4 = *(const float4*)(g_P    + cb + (size_t)gg*Dn*Nn);
            float4 E4 = *(const float4*)(g_hend + cb + (size_t)gg*Dn*Nn);
            h[0] = fmaf(h[0], P4.x, E4.x);
            h[1] = fmaf(h[1], P4.y, E4.y);
            h[2] = fmaf(h[2], P4.z, E4.z);
            h[3] = fmaf(h[3], P4.w, E4.w);
        }
    }

    int rev = (k>>1)&1;
    const float* usrc  = dir_src((k&1)|((k&4)>>1), x) + ((size_t)b*Dn + dc*32)*Ln;
    const float* dlt_g = g_delta + ((size_t)(b*Kn+k)*Dn + dc*32)*Ln + g*SEG;
    const float* BCg   = g_BC + (size_t)(b*Kn+k)*32*Ln + g*SEG;
    float*       ys_g  = g_ys + ((size_t)(b*Kn+k)*Dn + dc*32)*Ln + g*SEG;

    int drow = dl*PT2;

    for(int c0=0;c0<SEG;c0+=32){
        int l0 = g*SEG + c0;
        for(int i=tid;i<256;i+=128){
            int dd = i>>3, q = i&7;
            float4 dv = *(const float4*)(dlt_g + (size_t)dd*Ln + c0 + q*4);
            float4 uv;
            const float* urow = usrc + (size_t)dd*Ln;
            if(!rev){ uv = *(const float4*)(urow + l0 + q*4); }
            else { float4 r = *(const float4*)(urow + (Ln-4-l0-q*4));
                   uv.x=r.w; uv.y=r.z; uv.z=r.y; uv.w=r.x; }
            *(float4*)&sdl[dd*PT2 + q*4] = dv;
            *(float4*)&su [dd*PT2 + q*4] = uv;
        }
        {
            int i = tid;  // 128 covers 16n x 8q exactly
            int n = i>>3, q = i&7;
            float bv[4]; *(float4*)bv = *(const float4*)(BCg + (size_t)n*Ln + c0 + q*4);
            float cv[4]; *(float4*)cv = *(const float4*)(BCg + (size_t)(16+n)*Ln + c0 + q*4);
            #pragma unroll
            for(int j=0;j<4;j++){ sB[(q*4+j)*16 + n] = bv[j]; sC[(q*4+j)*16 + n] = cv[j]; }
        }
        __syncthreads();
        for(int t4=0;t4<32;t4+=4){
            float dv[4]; *(float4*)dv = *(const float4*)&sdl[drow+t4];
            float uv[4]; *(float4*)uv = *(const float4*)&su [drow+t4];
            #pragma unroll
            for(int j=0;j<4;j++){
                float dlt = dv[j], uu = uv[j];
                float du = dlt*uu;
                float bt[4]; *(float4*)bt = *(const float4*)&sB[(t4+j)*16 + n0];
                float ct[4]; *(float4*)ct = *(const float4*)&sC[(t4+j)*16 + n0];
                float p = 0.f;
                #pragma unroll
                for(int i=0;i<4;i++){
                    float dA;
                    asm("ex2.approx.ftz.f32 %0, %1;" : "=f"(dA) : "f"(dlt*a2[i]));
                    h[i] = fmaf(h[i], dA, du*bt[i]);
                    p = fmaf(h[i], ct[i], p);
                }
                p += __shfl_xor_sync(0xffffffffu, p, 1);
                p += __shfl_xor_sync(0xffffffffu, p, 2);
                if(sl == 0) sy[drow+t4+j] = fmaf(Dd, uu, p);
            }
        }
        __syncthreads();
        for(int i=tid;i<256;i+=128){
            int dd = i>>3, q = i&7;
            *(float4*)(ys_g + (size_t)dd*Ln + c0 + q*4) = *(const float4*)&sy[dd*PT2 + q*4];
        }
        __syncthreads();
    }
}

// ---------------------------------------------------------------------------
// kmerge: cross-merge via 64x65 smem tiles.
// ---------------------------------------------------------------------------
__global__ void __launch_bounds__(256) kmerge(){
    __shared__ float buf[64*65];
    int tid = threadIdx.x;
    int d = blockIdx.x, b = blockIdx.y;
    const float* base = g_ys + (size_t)b*Kn*Dn*Ln + (size_t)d*Ln;

    float acc[16];
    #pragma unroll
    for(int i=0;i<16;i++){
        int l = tid + i*256;
        acc[i] = base[(size_t)0*Dn*Ln + l] + base[(size_t)2*Dn*Ln + (Ln-1-l)];
    }
    for(int i=tid;i<Ln;i+=256)
        buf[(i>>6)*65 + (i&63)] = base[(size_t)1*Dn*Ln + i] + base[(size_t)3*Dn*Ln + (Ln-1-i)];
    __syncthreads();
    #pragma unroll
    for(int i=0;i<16;i++){
        int l = tid + i*256; int h = l>>6, w = l&63;
        acc[i] += buf[w*65 + h];
    }
    __syncthreads();
    for(int i=tid;i<Ln;i+=256)
        buf[(i>>6)*65 + (i&63)] = base[(size_t)4*Dn*Ln + i] + base[(size_t)6*Dn*Ln + (Ln-1-i)];
    __syncthreads();
    #pragma unroll
    for(int i=0;i<16;i++){
        int l = tid + i*256; int h = l>>6, w = l&63;
        acc[i] += buf[((w-h)&63)*65 + h];
    }
    __syncthreads();
    for(int i=tid;i<Ln;i+=256)
        buf[(i>>6)*65 + (i&63)] = base[(size_t)5*Dn*Ln + i] + base[(size_t)7*Dn*Ln + (Ln-1-i)];
    __syncthreads();
    #pragma unroll
    for(int i=0;i<16;i++){
        int l = tid + i*256; int h = l>>6, w = l&63;
        acc[i] += buf[((w+h)&63)*65 + h];
    }
    float* yout = g_y + ((size_t)b*Dn + d)*Ln;
    #pragma unroll
    for(int i=0;i<16;i++) yout[tid + i*256] = acc[i];
}

// ---------------------------------------------------------------------------
// kln: LayerNorm over D with transpose.
// ---------------------------------------------------------------------------
__global__ void __launch_bounds__(256) kln(const float* __restrict__ lnw,
                                           const float* __restrict__ lnb,
                                           float* __restrict__ out){
    __shared__ float sT[Dn*33];
    __shared__ float sred[8*32], sredq[8*32];
    __shared__ float smu[32], srs[32];
    int tid = threadIdx.x;
    int lt = blockIdx.x, b = blockIdx.y;

    const float* ybase = g_y + (size_t)b*Dn*Ln + (size_t)lt*32;
    for(int i=tid;i<Dn*32;i+=256){
        int d = i>>5, ll = i&31;
        sT[d*33+ll] = ybase[(size_t)d*Ln + ll];
    }
    __syncthreads();

    int g = tid >> 5, ll = tid & 31;
    float s=0.f, sq=0.f;
    for(int d=g*24; d<g*24+24; d++){
        float v = sT[d*33+ll];
        s += v; sq = fmaf(v, v, sq);
    }
    sred[g*32+ll]=s; sredq[g*32+ll]=sq;
    __syncthreads();
    if(tid < 32){
        float S=0.f, Q=0.f;
        #pragma unroll
        for(int gg=0;gg<8;gg++){ S += sred[gg*32+tid]; Q += sredq[gg*32+tid]; }
        float mu  = S * (1.f/192.f);
        float var = Q * (1.f/192.f) - mu*mu;
        smu[tid] = mu;
        srs[tid] = rsqrtf(var + 1e-5f);
    }
    __syncthreads();

    float* obase = out + ((size_t)b*Ln + (size_t)lt*32)*Dn;
    for(int i=tid;i<32*Dn;i+=256){
        int l = i/Dn, d = i - l*Dn;
        float v = (sT[d*33+l] - smu[l]) * srs[l];
        obase[(size_t)l*Dn + d] = fmaf(v, lnw[d], lnb[d]);
    }
}

// ---------------------------------------------------------------------------
extern "C" void kernel_launch(void* const* d_in, const int* in_sizes, int n_in,
                              void* d_out, int out_size){
    const float* x   = (const float*)d_in[0];
    const float* xw  = (const float*)d_in[1];
    const float* dtw = (const float*)d_in[2];
    const float* dtb = (const float*)d_in[3];
    const float* alg = (const float*)d_in[4];
    const float* Ds  = (const float*)d_in[5];
    const float* lnw = (const float*)d_in[6];
    const float* lnb = (const float*)d_in[7];
    float* out = (float*)d_out;

    kprep <<<dim3(Dn, Bn),        256>>>(x);
    kproj <<<dim3(64, Kn, Bn),    256>>>(x, xw, dtw, dtb);
    kpass1<<<dim3(6, G*Kn, Bn),   128>>>(x, alg);
    kpass2<<<dim3(6, G*Kn, Bn),   128>>>(x, alg, Ds);
    kmerge<<<dim3(Dn, Bn),        256>>>();
    kln   <<<dim3(128, Bn),       256>>>(lnw, lnb, out);
}